// round 2
// baseline (speedup 1.0000x reference)
#include <cuda_runtime.h>
#include <math.h>

#define NB   2048
#define NTOK 176
#define NQ   128

// Scratch (allocation-free rule: device globals)
__device__ float g_KT[NB * 64 * NTOK];   // [b][d][k]
__device__ float g_V [NB * NTOK * 64];   // [b][k][d]
__device__ float g_QT[NB * 64 * NQ];     // [b][d][q]
__device__ int   g_afmt;                 // 0=u8, 1=int32, 2=float32

#define SWZ(g, r) ((((g) ^ (r) ^ ((r) >> 3))) & 31)

// ---------------------------------------------------------------------------
// classify prey_is_alive storage format (deterministic, data-driven)
// ---------------------------------------------------------------------------
__global__ void classify_kernel(const unsigned int* __restrict__ w) {
    __shared__ int sF, sB;
    if (threadIdx.x == 0) { sF = 0; sB = 0; }
    __syncthreads();
    int lf = 0, lb = 0;
    for (int i = threadIdx.x; i < 65536; i += 256) {
        unsigned int v = w[i];
        if (v == 0x3F800000u) lf = 1;
        else if (v > 1u) lb = 1;
    }
    if (lf) atomicOr(&sF, 1);
    if (lb) atomicOr(&sB, 1);
    __syncthreads();
    if (threadIdx.x == 0) g_afmt = sF ? 2 : (sB ? 0 : 1);
}

// ---------------------------------------------------------------------------
// Kernel 1: entity FFN encoders + K/V/Q projections
// 2816 blocks x 256 threads; each block = 128 tokens of one entity type.
// ---------------------------------------------------------------------------
__global__ void __launch_bounds__(256) encode_kernel(
    const float* __restrict__ pred_state, const float* __restrict__ prey_state,
    const float* __restrict__ obst_state, const float* __restrict__ emb,
    const float* __restrict__ p_w1, const float* __restrict__ p_b1,
    const float* __restrict__ p_w2, const float* __restrict__ p_b2,
    const float* __restrict__ y_w1, const float* __restrict__ y_b1,
    const float* __restrict__ y_w2, const float* __restrict__ y_b2,
    const float* __restrict__ o_w1, const float* __restrict__ o_b1,
    const float* __restrict__ o_w2, const float* __restrict__ o_b2,
    const float* __restrict__ wq, const float* __restrict__ bq,
    const float* __restrict__ wk, const float* __restrict__ bk,
    const float* __restrict__ wv, const float* __restrict__ bv)
{
    extern __shared__ float sm[];
    float* sW2 = sm;            // 4096
    float* sWK = sm + 4096;     // 4096
    float* sWV = sm + 8192;     // 4096
    float* sWQ = sm + 12288;    // 4096
    float* sH  = sm + 16384;    // [64][128]
    float* sX  = sm + 24576;    // [64][128] swizzled
    float* sC  = sm + 32768;    // 64
    float* sBK = sm + 32832;    // 64
    float* sBV = sm + 32896;    // 64
    float* sBQ = sm + 32960;    // 64
    float* sW1 = sm + 33024;    // 192
    float* sB1 = sm + 33216;    // 64
    float* sSt = sm + 33280;    // 384

    const int tid = threadIdx.x;
    const int blk = blockIdx.x;

    int type, inDim, perShift, slotBase, tok0;
    const float *state, *w1, *b1, *w2, *b2;
    if (blk < 256)       { type = 0; tok0 = blk * 128;          state = pred_state; w1 = p_w1; b1 = p_b1; w2 = p_w2; b2 = p_b2; inDim = 2; perShift = 4; slotBase = 0;   }
    else if (blk < 2304) { type = 1; tok0 = (blk - 256)  * 128; state = prey_state; w1 = y_w1; b1 = y_b1; w2 = y_w2; b2 = y_b2; inDim = 2; perShift = 7; slotBase = 16;  }
    else                 { type = 2; tok0 = (blk - 2304) * 128; state = obst_state; w1 = o_w1; b1 = o_b1; w2 = o_w2; b2 = o_b2; inDim = 3; perShift = 5; slotBase = 144; }

    for (int i = tid; i < 4096; i += 256) { sW2[i] = w2[i]; sWK[i] = wk[i]; sWV[i] = wv[i]; }
    if (type == 1)
        for (int i = tid; i < 4096; i += 256) sWQ[i] = wq[i];
    if (tid < 64) {
        sC[tid]  = b2[tid] + emb[type * 64 + tid];
        sBK[tid] = bk[tid];
        sBV[tid] = bv[tid];
        sBQ[tid] = bq[tid];
        sB1[tid] = b1[tid];
    }
    if (tid < inDim * 64) sW1[tid] = w1[tid];
    for (int i = tid; i < 128 * inDim; i += 256) {
        int t = i / inDim, j = i - t * inDim;
        sSt[t * 3 + j] = state[(tok0 + t) * inDim + j];
    }
    __syncthreads();

    // H[d][tok] = relu(state @ w1 + b1), stored transposed
    for (int e = tid; e < 8192; e += 256) {
        int k = e >> 7, t = e & 127;
        float a = sB1[k];
        for (int j = 0; j < inDim; j++) a += sSt[t * 3 + j] * sW1[j * 64 + k];
        sH[k * 128 + t] = fmaxf(a, 0.f);
    }
    __syncthreads();

    const int dg = tid & 7, tg = tid >> 3, ds = dg * 8;

    // X = H @ W2 + (b2 + emb)  -> sX transposed, swizzled
    {
        float acc[4][8];
#pragma unroll
        for (int i = 0; i < 4; i++)
#pragma unroll
            for (int j = 0; j < 8; j++) acc[i][j] = 0.f;
#pragma unroll 4
        for (int k = 0; k < 64; k++) {
            float4 a4  = *(const float4*)(sH  + k * 128 + tg * 4);
            float4 b0  = *(const float4*)(sW2 + k * 64 + ds);
            float4 b1v = *(const float4*)(sW2 + k * 64 + ds + 4);
            float av[4] = {a4.x, a4.y, a4.z, a4.w};
            float bw[8] = {b0.x, b0.y, b0.z, b0.w, b1v.x, b1v.y, b1v.z, b1v.w};
#pragma unroll
            for (int i = 0; i < 4; i++)
#pragma unroll
                for (int j = 0; j < 8; j++) acc[i][j] += av[i] * bw[j];
        }
#pragma unroll
        for (int j = 0; j < 8; j++) {
            int d = ds + j;
            float c = sC[d];
            *(float4*)(sX + d * 128 + SWZ(tg, d) * 4) =
                make_float4(acc[0][j] + c, acc[1][j] + c, acc[2][j] + c, acc[3][j] + c);
        }
    }
    __syncthreads();

    const int gT   = tok0 + tg * 4;
    const int b    = gT >> perShift;
    const int lp   = gT & ((1 << perShift) - 1);
    const int slot = slotBase + lp;

    // fused K,V projections
    {
        float aK[4][8], aV[4][8];
#pragma unroll
        for (int i = 0; i < 4; i++)
#pragma unroll
            for (int j = 0; j < 8; j++) { aK[i][j] = 0.f; aV[i][j] = 0.f; }
#pragma unroll 2
        for (int k = 0; k < 64; k++) {
            float4 a4  = *(const float4*)(sX  + k * 128 + SWZ(tg, k) * 4);
            float4 k0  = *(const float4*)(sWK + k * 64 + ds);
            float4 k1  = *(const float4*)(sWK + k * 64 + ds + 4);
            float4 v0  = *(const float4*)(sWV + k * 64 + ds);
            float4 v1  = *(const float4*)(sWV + k * 64 + ds + 4);
            float av[4] = {a4.x, a4.y, a4.z, a4.w};
            float kw[8] = {k0.x, k0.y, k0.z, k0.w, k1.x, k1.y, k1.z, k1.w};
            float vw[8] = {v0.x, v0.y, v0.z, v0.w, v1.x, v1.y, v1.z, v1.w};
#pragma unroll
            for (int i = 0; i < 4; i++)
#pragma unroll
                for (int j = 0; j < 8; j++) {
                    aK[i][j] += av[i] * kw[j];
                    aV[i][j] += av[i] * vw[j];
                }
        }
#pragma unroll
        for (int j = 0; j < 8; j++) {
            int d = ds + j;
            float bb = sBK[d];
            *(float4*)(g_KT + (b * 64 + d) * 176 + slot) =
                make_float4(aK[0][j] + bb, aK[1][j] + bb, aK[2][j] + bb, aK[3][j] + bb);
        }
#pragma unroll
        for (int i = 0; i < 4; i++) {
            int row = (b * 176 + slot + i) * 64;
            *(float4*)(g_V + row + ds) =
                make_float4(aV[i][0] + sBV[ds],     aV[i][1] + sBV[ds + 1],
                            aV[i][2] + sBV[ds + 2], aV[i][3] + sBV[ds + 3]);
            *(float4*)(g_V + row + ds + 4) =
                make_float4(aV[i][4] + sBV[ds + 4], aV[i][5] + sBV[ds + 5],
                            aV[i][6] + sBV[ds + 6], aV[i][7] + sBV[ds + 7]);
        }
    }

    if (type == 1) {
        float aQ[4][8];
#pragma unroll
        for (int i = 0; i < 4; i++)
#pragma unroll
            for (int j = 0; j < 8; j++) aQ[i][j] = 0.f;
#pragma unroll 4
        for (int k = 0; k < 64; k++) {
            float4 a4 = *(const float4*)(sX  + k * 128 + SWZ(tg, k) * 4);
            float4 q0 = *(const float4*)(sWQ + k * 64 + ds);
            float4 q1 = *(const float4*)(sWQ + k * 64 + ds + 4);
            float av[4] = {a4.x, a4.y, a4.z, a4.w};
            float qw[8] = {q0.x, q0.y, q0.z, q0.w, q1.x, q1.y, q1.z, q1.w};
#pragma unroll
            for (int i = 0; i < 4; i++)
#pragma unroll
                for (int j = 0; j < 8; j++) aQ[i][j] += av[i] * qw[j];
        }
#pragma unroll
        for (int j = 0; j < 8; j++) {
            int d = ds + j;
            float bb = sBQ[d];
            *(float4*)(g_QT + (b * 64 + d) * 128 + lp) =
                make_float4(aQ[0][j] + bb, aQ[1][j] + bb, aQ[2][j] + bb, aQ[3][j] + bb);
        }
    }
}

// ---------------------------------------------------------------------------
// head gemm helper: Out[d][q](swz) = act(A[64xq](swz) @ Wg[64x64] + bg)
// ---------------------------------------------------------------------------
__device__ __forceinline__ void head_gemm(
    const float* __restrict__ A, const float* __restrict__ Wg,
    const float* __restrict__ bg, float* __restrict__ Out,
    int tg, int ds, bool doRelu)
{
    float acc[4][8];
#pragma unroll
    for (int i = 0; i < 4; i++)
#pragma unroll
        for (int j = 0; j < 8; j++) acc[i][j] = 0.f;
#pragma unroll 4
    for (int k = 0; k < 64; k++) {
        float4 a4 = *(const float4*)(A + k * 128 + SWZ(tg, k) * 4);
        float4 b0 = *(const float4*)(Wg + k * 64 + ds);
        float4 b1 = *(const float4*)(Wg + k * 64 + ds + 4);
        float av[4] = {a4.x, a4.y, a4.z, a4.w};
        float bw[8] = {b0.x, b0.y, b0.z, b0.w, b1.x, b1.y, b1.z, b1.w};
#pragma unroll
        for (int i = 0; i < 4; i++)
#pragma unroll
            for (int j = 0; j < 8; j++) acc[i][j] += av[i] * bw[j];
    }
#pragma unroll
    for (int j = 0; j < 8; j++) {
        int d = ds + j;
        float bb = bg[d];
        float o0 = acc[0][j] + bb, o1 = acc[1][j] + bb, o2 = acc[2][j] + bb, o3 = acc[3][j] + bb;
        if (doRelu) { o0 = fmaxf(o0, 0.f); o1 = fmaxf(o1, 0.f); o2 = fmaxf(o2, 0.f); o3 = fmaxf(o3, 0.f); }
        *(float4*)(Out + d * 128 + SWZ(tg, d) * 4) = make_float4(o0, o1, o2, o3);
    }
}

// ---------------------------------------------------------------------------
// Kernel 2: attention + head, one CTA per batch, 256 threads
// ---------------------------------------------------------------------------
__global__ void __launch_bounds__(256) attn_kernel(
    const float* __restrict__ pred_state, const float* __restrict__ prey_state,
    const float* __restrict__ obst_state, const void* __restrict__ alive,
    const float* __restrict__ w_pos,
    const float* __restrict__ wo,   const float* __restrict__ bo,
    const float* __restrict__ n_w1, const float* __restrict__ n_b1,
    const float* __restrict__ n_w2, const float* __restrict__ n_b2,
    const float* __restrict__ n_w3, const float* __restrict__ n_b3,
    float* __restrict__ out)
{
    extern __shared__ float sm[];
    float* sKT = sm;                // 11264  [d][k]
    float* sQT = sm + 11264;        // 8192   [d][q]   (later X0)
    float* sV  = sm + 19456;        // 11264  [k][d]   (later X1)
    float* sS  = sm + 30720;        // 22528  [k][q]   (swizzled)
    float* sBK = sm + 53248;        // 176
    float* sMK = sm + 53424;        // 176
    float* sDQ = sm + 53600;        // 128
    float* sIv = sm + 53728;        // 128

    const int tid = threadIdx.x;
    const int b   = blockIdx.x;

    {
        const float4* gk = (const float4*)(g_KT + b * 11264);
        const float4* gq = (const float4*)(g_QT + b * 8192);
        const float4* gv = (const float4*)(g_V  + b * 11264);
        float4* dk = (float4*)sKT;
        float4* dq = (float4*)sQT;
        float4* dv = (float4*)sV;
        for (int i = tid; i < 2816; i += 256) dk[i] = gk[i];
        for (int i = tid; i < 2048; i += 256) dq[i] = gq[i];
        for (int i = tid; i < 2816; i += 256) dv[i] = gv[i];
    }

    const int fmt = g_afmt;
    if (tid < 176) {
        int k = tid;
        float p0, p1, mk = 0.f;
        if (k < 16) {
            p0 = pred_state[(b * 16 + k) * 2];
            p1 = pred_state[(b * 16 + k) * 2 + 1];
        } else if (k < 144) {
            int j = k - 16;
            p0 = prey_state[(b * 128 + j) * 2];
            p1 = prey_state[(b * 128 + j) * 2 + 1];
            bool al;
            if (fmt == 0)      al = ((const unsigned char*)alive)[b * 128 + j] != 0;
            else if (fmt == 1) al = ((const int*)alive)[b * 128 + j] != 0;
            else               al = ((const float*)alive)[b * 128 + j] != 0.f;
            if (!al) mk = -1e9f;
        } else {
            int j = k - 144;
            p0 = obst_state[(b * 32 + j) * 3];
            p1 = obst_state[(b * 32 + j) * 3 + 1];
        }
        sBK[k] = p0 * w_pos[0] + p1 * w_pos[1];
        sMK[k] = mk;
    }
    if (tid < 128) {
        int q = tid;
        bool al;
        if (fmt == 0)      al = ((const unsigned char*)alive)[b * 128 + q] != 0;
        else if (fmt == 1) al = ((const int*)alive)[b * 128 + q] != 0;
        else               al = ((const float*)alive)[b * 128 + q] != 0.f;
        sDQ[q] = al ? 0.f : 1.f;
    }
    __syncthreads();

    // GEMM1: S[k][q] = (K.Q - bias_k)/8 (+ mask); bias_q cancels in softmax
    for (int t = tid; t < 352; t += 256) {
        int kg = t >> 4, qg = t & 15;
        float acc[8][8];
#pragma unroll
        for (int i = 0; i < 8; i++)
#pragma unroll
            for (int j = 0; j < 8; j++) acc[i][j] = 0.f;
#pragma unroll 4
        for (int d = 0; d < 64; d++) {
            float4 k0 = *(const float4*)(sKT + d * 176 + kg * 8);
            float4 k1 = *(const float4*)(sKT + d * 176 + kg * 8 + 4);
            float4 q0 = *(const float4*)(sQT + d * 128 + qg * 8);
            float4 q1 = *(const float4*)(sQT + d * 128 + qg * 8 + 4);
            float kv[8] = {k0.x, k0.y, k0.z, k0.w, k1.x, k1.y, k1.z, k1.w};
            float qv[8] = {q0.x, q0.y, q0.z, q0.w, q1.x, q1.y, q1.z, q1.w};
#pragma unroll
            for (int i = 0; i < 8; i++)
#pragma unroll
                for (int j = 0; j < 8; j++) acc[i][j] += kv[i] * qv[j];
        }
#pragma unroll
        for (int i = 0; i < 8; i++) {
            int r = kg * 8 + i;
            float bk = sBK[r], mk = sMK[r];
            float s[8];
#pragma unroll
            for (int j = 0; j < 8; j++) {
                int q = qg * 8 + j;
                s[j] = (acc[i][j] - bk) * 0.125f + sDQ[q] * mk;
            }
            *(float4*)(sS + r * 128 + SWZ(qg * 2,     r) * 4) = make_float4(s[0], s[1], s[2], s[3]);
            *(float4*)(sS + r * 128 + SWZ(qg * 2 + 1, r) * 4) = make_float4(s[4], s[5], s[6], s[7]);
        }
    }
    __syncthreads();

    // softmax: paired lanes (each pair owns one query, 88 keys each)
    {
        int q = tid >> 1, h = tid & 1;
        int g = q >> 2, qr = q & 3;
        int k0 = h ? 88 : 0, k1 = h ? 176 : 88;
        float m = -3.4e38f;
        for (int k = k0; k < k1; k++)
            m = fmaxf(m, sS[k * 128 + SWZ(g, k) * 4 + qr]);
        m = fmaxf(m, __shfl_xor_sync(0xFFFFFFFFu, m, 1));
        float ssum = 0.f;
        for (int k = k0; k < k1; k++) {
            int idx = k * 128 + SWZ(g, k) * 4 + qr;
            float p = __expf(sS[idx] - m);
            ssum += p;
            sS[idx] = p;
        }
        ssum += __shfl_xor_sync(0xFFFFFFFFu, ssum, 1);
        if (h == 0) sIv[q] = 1.f / ssum;
    }
    __syncthreads();

    const int dg = tid & 7, tg = tid >> 3, ds = dg * 8;
    float* sX0 = sQT;
    float* sX1 = sV;

    // GEMM2: attn_out = P @ V (normalized by sIv), -> sX0 transposed
    {
        float acc[4][8];
#pragma unroll
        for (int i = 0; i < 4; i++)
#pragma unroll
            for (int j = 0; j < 8; j++) acc[i][j] = 0.f;
#pragma unroll 2
        for (int k = 0; k < 176; k++) {
            float4 p4 = *(const float4*)(sS + k * 128 + SWZ(tg, k) * 4);
            float4 v0 = *(const float4*)(sV + k * 64 + ds);
            float4 v1 = *(const float4*)(sV + k * 64 + ds + 4);
            float pv[4] = {p4.x, p4.y, p4.z, p4.w};
            float vv[8] = {v0.x, v0.y, v0.z, v0.w, v1.x, v1.y, v1.z, v1.w};
#pragma unroll
            for (int i = 0; i < 4; i++)
#pragma unroll
                for (int j = 0; j < 8; j++) acc[i][j] += pv[i] * vv[j];
        }
        float iv[4];
#pragma unroll
        for (int i = 0; i < 4; i++) iv[i] = sIv[tg * 4 + i];
        __syncthreads();   // all V reads done before sX1(=sV) is written later; safe point
#pragma unroll
        for (int j = 0; j < 8; j++) {
            int d = ds + j;
            *(float4*)(sX0 + d * 128 + SWZ(tg, d) * 4) =
                make_float4(acc[0][j] * iv[0], acc[1][j] * iv[1],
                            acc[2][j] * iv[2], acc[3][j] * iv[3]);
        }
    }
    __syncthreads();

    head_gemm(sX0, wo,   bo,   sX1, tg, ds, false);
    __syncthreads();
    head_gemm(sX1, n_w1, n_b1, sX0, tg, ds, true);
    __syncthreads();
    head_gemm(sX0, n_w2, n_b2, sX1, tg, ds, true);
    __syncthreads();

    if (tid < 128) {
        int q = tid, g = q >> 2, qr = q & 3;
        float a = n_b3[0];
#pragma unroll 8
        for (int d = 0; d < 64; d++)
            a += sX1[d * 128 + SWZ(g, d) * 4 + qr] * n_w3[d];
        out[b * 128 + q] = tanhf(a);
    }
}

// ---------------------------------------------------------------------------
extern "C" void kernel_launch(void* const* d_in, const int* in_sizes, int n_in,
                              void* d_out, int out_size)
{
    const float* pred  = (const float*)d_in[0];
    const float* prey  = (const float*)d_in[1];
    const float* obst  = (const float*)d_in[2];
    const void*  alive = d_in[3];
    const float* emb   = (const float*)d_in[4];
    const float* p_w1 = (const float*)d_in[5],  *p_b1 = (const float*)d_in[6];
    const float* p_w2 = (const float*)d_in[7],  *p_b2 = (const float*)d_in[8];
    const float* y_w1 = (const float*)d_in[9],  *y_b1 = (const float*)d_in[10];
    const float* y_w2 = (const float*)d_in[11], *y_b2 = (const float*)d_in[12];
    const float* o_w1 = (const float*)d_in[13], *o_b1 = (const float*)d_in[14];
    const float* o_w2 = (const float*)d_in[15], *o_b2 = (const float*)d_in[16];
    const float* wq = (const float*)d_in[17], *bq = (const float*)d_in[18];
    const float* wk = (const float*)d_in[19], *bk = (const float*)d_in[20];
    const float* wv = (const float*)d_in[21], *bv = (const float*)d_in[22];
    const float* wo = (const float*)d_in[23], *bo = (const float*)d_in[24];
    const float* w_pos = (const float*)d_in[25];
    const float* n_w1 = (const float*)d_in[26], *n_b1 = (const float*)d_in[27];
    const float* n_w2 = (const float*)d_in[28], *n_b2 = (const float*)d_in[29];
    const float* n_w3 = (const float*)d_in[30], *n_b3 = (const float*)d_in[31];
    float* out = (float*)d_out;

    cudaFuncSetAttribute(encode_kernel, cudaFuncAttributeMaxDynamicSharedMemorySize, 33664 * 4);
    cudaFuncSetAttribute(attn_kernel,   cudaFuncAttributeMaxDynamicSharedMemorySize, 53856 * 4);

    classify_kernel<<<1, 256>>>((const unsigned int*)alive);
    encode_kernel<<<2816, 256, 33664 * 4>>>(pred, prey, obst, emb,
        p_w1, p_b1, p_w2, p_b2, y_w1, y_b1, y_w2, y_b2, o_w1, o_b1, o_w2, o_b2,
        wq, bq, wk, bk, wv, bv);
    attn_kernel<<<2048, 256, 53856 * 4>>>(pred, prey, obst, alive, w_pos,
        wo, bo, n_w1, n_b1, n_w2, n_b2, n_w3, n_b3, out);
}

// round 3
// speedup vs baseline: 1.0891x; 1.0891x over previous
#include <cuda_runtime.h>
#include <math.h>

#define NB   2048
#define NTOK 176
#define NQ   128

// Scratch (allocation-free rule: device globals)
__device__ float g_KT[NB * 64 * NTOK];   // [b][d][k]
__device__ float g_V [NB * NTOK * 64];   // [b][k][d]
__device__ float g_QT[NB * 64 * NQ];     // [b][d][q]

#define SWZ(g, r) ((((g) ^ (r) ^ ((r) >> 3))) & 31)

// ---------------------------------------------------------------------------
// Kernel 1: entity FFN encoders + K/V/Q projections
// 2816 blocks x 256 threads; each block = 128 tokens of one entity type.
// smem ~99.5KB -> 2 CTAs/SM.
// ---------------------------------------------------------------------------
__global__ void __launch_bounds__(256, 2) encode_kernel(
    const float* __restrict__ pred_state, const float* __restrict__ prey_state,
    const float* __restrict__ obst_state, const float* __restrict__ emb,
    const float* __restrict__ p_w1, const float* __restrict__ p_b1,
    const float* __restrict__ p_w2, const float* __restrict__ p_b2,
    const float* __restrict__ y_w1, const float* __restrict__ y_b1,
    const float* __restrict__ y_w2, const float* __restrict__ y_b2,
    const float* __restrict__ o_w1, const float* __restrict__ o_b1,
    const float* __restrict__ o_w2, const float* __restrict__ o_b2,
    const float* __restrict__ wq, const float* __restrict__ bq,
    const float* __restrict__ wk, const float* __restrict__ bk,
    const float* __restrict__ wv, const float* __restrict__ bv)
{
    extern __shared__ float sm[];
    float* sW2 = sm;            // 4096
    float* sWK = sm + 4096;     // 4096
    float* sWV = sm + 8192;     // 4096
    float* sHQ = sm + 12288;    // 4096: H half [32][128], later WQ
    float* sX  = sm + 16384;    // [64][128] swizzled
    float* sC  = sm + 24576;    // 64
    float* sBK = sm + 24640;    // 64
    float* sBV = sm + 24704;    // 64
    float* sBQ = sm + 24768;    // 64
    float* sB1 = sm + 24832;    // 64
    float* sW1 = sm + 24896;    // 192
    float* sSt = sm + 25088;    // 384   (total 25472 floats)

    const int tid = threadIdx.x;
    const int blk = blockIdx.x;

    int type, inDim, perShift, slotBase, tok0;
    const float *state, *w1, *b1, *w2, *b2;
    if (blk < 256)       { type = 0; tok0 = blk * 128;          state = pred_state; w1 = p_w1; b1 = p_b1; w2 = p_w2; b2 = p_b2; inDim = 2; perShift = 4; slotBase = 0;   }
    else if (blk < 2304) { type = 1; tok0 = (blk - 256)  * 128; state = prey_state; w1 = y_w1; b1 = y_b1; w2 = y_w2; b2 = y_b2; inDim = 2; perShift = 7; slotBase = 16;  }
    else                 { type = 2; tok0 = (blk - 2304) * 128; state = obst_state; w1 = o_w1; b1 = o_b1; w2 = o_w2; b2 = o_b2; inDim = 3; perShift = 5; slotBase = 144; }

    for (int i = tid; i < 4096; i += 256) { sW2[i] = w2[i]; sWK[i] = wk[i]; sWV[i] = wv[i]; }
    if (tid < 64) {
        sC[tid]  = b2[tid] + emb[type * 64 + tid];
        sBK[tid] = bk[tid];
        sBV[tid] = bv[tid];
        sBQ[tid] = bq[tid];
        sB1[tid] = b1[tid];
    }
    if (tid < inDim * 64) sW1[tid] = w1[tid];
    for (int i = tid; i < 128 * inDim; i += 256) {
        int t = i / inDim, j = i - t * inDim;
        sSt[t * 3 + j] = state[(tok0 + t) * inDim + j];
    }
    __syncthreads();

    const int dg = tid & 7, tg = tid >> 3, ds = dg * 8;

    // X = H @ W2 accumulated over two 32-k halves (H half lives in sHQ)
    float accX[4][8];
#pragma unroll
    for (int i = 0; i < 4; i++)
#pragma unroll
        for (int j = 0; j < 8; j++) accX[i][j] = 0.f;

#pragma unroll 1
    for (int h = 0; h < 2; h++) {
        // H[h*32+k][t] = relu(state @ w1 + b1)
        for (int e = tid; e < 4096; e += 256) {
            int k = e >> 7, t = e & 127;
            int gk = h * 32 + k;
            float a = sB1[gk];
            for (int j = 0; j < inDim; j++) a += sSt[t * 3 + j] * sW1[j * 64 + gk];
            sHQ[k * 128 + t] = fmaxf(a, 0.f);
        }
        __syncthreads();
#pragma unroll 4
        for (int kk = 0; kk < 32; kk++) {
            float4 a4  = *(const float4*)(sHQ + kk * 128 + tg * 4);
            float4 b0  = *(const float4*)(sW2 + (h * 32 + kk) * 64 + ds);
            float4 b1v = *(const float4*)(sW2 + (h * 32 + kk) * 64 + ds + 4);
            float av[4] = {a4.x, a4.y, a4.z, a4.w};
            float bw[8] = {b0.x, b0.y, b0.z, b0.w, b1v.x, b1v.y, b1v.z, b1v.w};
#pragma unroll
            for (int i = 0; i < 4; i++)
#pragma unroll
                for (int j = 0; j < 8; j++) accX[i][j] += av[i] * bw[j];
        }
        __syncthreads();
    }

    // write X (transposed, swizzled); prey CTAs also stream WQ into sHQ (dead)
#pragma unroll
    for (int j = 0; j < 8; j++) {
        int d = ds + j;
        float c = sC[d];
        *(float4*)(sX + d * 128 + SWZ(tg, d) * 4) =
            make_float4(accX[0][j] + c, accX[1][j] + c, accX[2][j] + c, accX[3][j] + c);
    }
    if (type == 1)
        for (int i = tid; i < 4096; i += 256) sHQ[i] = wq[i];
    __syncthreads();

    const int gT   = tok0 + tg * 4;
    const int b    = gT >> perShift;
    const int lp   = gT & ((1 << perShift) - 1);
    const int slot = slotBase + lp;

    // fused K,V projections
    {
        float aK[4][8], aV[4][8];
#pragma unroll
        for (int i = 0; i < 4; i++)
#pragma unroll
            for (int j = 0; j < 8; j++) { aK[i][j] = 0.f; aV[i][j] = 0.f; }
#pragma unroll 2
        for (int k = 0; k < 64; k++) {
            float4 a4 = *(const float4*)(sX  + k * 128 + SWZ(tg, k) * 4);
            float4 k0 = *(const float4*)(sWK + k * 64 + ds);
            float4 k1 = *(const float4*)(sWK + k * 64 + ds + 4);
            float4 v0 = *(const float4*)(sWV + k * 64 + ds);
            float4 v1 = *(const float4*)(sWV + k * 64 + ds + 4);
            float av[4] = {a4.x, a4.y, a4.z, a4.w};
            float kw[8] = {k0.x, k0.y, k0.z, k0.w, k1.x, k1.y, k1.z, k1.w};
            float vw[8] = {v0.x, v0.y, v0.z, v0.w, v1.x, v1.y, v1.z, v1.w};
#pragma unroll
            for (int i = 0; i < 4; i++)
#pragma unroll
                for (int j = 0; j < 8; j++) {
                    aK[i][j] += av[i] * kw[j];
                    aV[i][j] += av[i] * vw[j];
                }
        }
#pragma unroll
        for (int j = 0; j < 8; j++) {
            int d = ds + j;
            float bb = sBK[d];
            *(float4*)(g_KT + (b * 64 + d) * 176 + slot) =
                make_float4(aK[0][j] + bb, aK[1][j] + bb, aK[2][j] + bb, aK[3][j] + bb);
        }
#pragma unroll
        for (int i = 0; i < 4; i++) {
            int row = (b * 176 + slot + i) * 64;
            *(float4*)(g_V + row + ds) =
                make_float4(aV[i][0] + sBV[ds],     aV[i][1] + sBV[ds + 1],
                            aV[i][2] + sBV[ds + 2], aV[i][3] + sBV[ds + 3]);
            *(float4*)(g_V + row + ds + 4) =
                make_float4(aV[i][4] + sBV[ds + 4], aV[i][5] + sBV[ds + 5],
                            aV[i][6] + sBV[ds + 6], aV[i][7] + sBV[ds + 7]);
        }
    }

    if (type == 1) {
        float aQ[4][8];
#pragma unroll
        for (int i = 0; i < 4; i++)
#pragma unroll
            for (int j = 0; j < 8; j++) aQ[i][j] = 0.f;
#pragma unroll 4
        for (int k = 0; k < 64; k++) {
            float4 a4 = *(const float4*)(sX  + k * 128 + SWZ(tg, k) * 4);
            float4 q0 = *(const float4*)(sHQ + k * 64 + ds);
            float4 q1 = *(const float4*)(sHQ + k * 64 + ds + 4);
            float av[4] = {a4.x, a4.y, a4.z, a4.w};
            float qw[8] = {q0.x, q0.y, q0.z, q0.w, q1.x, q1.y, q1.z, q1.w};
#pragma unroll
            for (int i = 0; i < 4; i++)
#pragma unroll
                for (int j = 0; j < 8; j++) aQ[i][j] += av[i] * qw[j];
        }
#pragma unroll
        for (int j = 0; j < 8; j++) {
            int d = ds + j;
            float bb = sBQ[d];
            *(float4*)(g_QT + (b * 64 + d) * 128 + lp) =
                make_float4(aQ[0][j] + bb, aQ[1][j] + bb, aQ[2][j] + bb, aQ[3][j] + bb);
        }
    }
}

// ---------------------------------------------------------------------------
// head gemm: Out[d][q](swz) = act(A[64xq](swz) @ Wg[64x64](smem) + bg)
// ---------------------------------------------------------------------------
__device__ __forceinline__ void head_gemm(
    const float* __restrict__ A, const float* __restrict__ Wg,
    const float* __restrict__ bg, float* __restrict__ Out,
    int tg, int ds, bool doRelu)
{
    float acc[4][8];
#pragma unroll
    for (int i = 0; i < 4; i++)
#pragma unroll
        for (int j = 0; j < 8; j++) acc[i][j] = 0.f;
#pragma unroll 4
    for (int k = 0; k < 64; k++) {
        float4 a4 = *(const float4*)(A + k * 128 + SWZ(tg, k) * 4);
        float4 b0 = *(const float4*)(Wg + k * 64 + ds);
        float4 b1 = *(const float4*)(Wg + k * 64 + ds + 4);
        float av[4] = {a4.x, a4.y, a4.z, a4.w};
        float bw[8] = {b0.x, b0.y, b0.z, b0.w, b1.x, b1.y, b1.z, b1.w};
#pragma unroll
        for (int i = 0; i < 4; i++)
#pragma unroll
            for (int j = 0; j < 8; j++) acc[i][j] += av[i] * bw[j];
    }
#pragma unroll
    for (int j = 0; j < 8; j++) {
        int d = ds + j;
        float bb = bg[d];
        float o0 = acc[0][j] + bb, o1 = acc[1][j] + bb, o2 = acc[2][j] + bb, o3 = acc[3][j] + bb;
        if (doRelu) { o0 = fmaxf(o0, 0.f); o1 = fmaxf(o1, 0.f); o2 = fmaxf(o2, 0.f); o3 = fmaxf(o3, 0.f); }
        *(float4*)(Out + d * 128 + SWZ(tg, d) * 4) = make_float4(o0, o1, o2, o3);
    }
}

// ---------------------------------------------------------------------------
// Kernel 2: attention + head, one CTA per batch, 256 threads.
// Keys padded 176 -> 192 (zeroed K/V, bias_k=+8e9 -> probs exactly 0).
// ---------------------------------------------------------------------------
#define NKP 192

__global__ void __launch_bounds__(256) attn_kernel(
    const float* __restrict__ pred_state, const float* __restrict__ prey_state,
    const float* __restrict__ obst_state, const void* __restrict__ alive,
    const float* __restrict__ w_pos,
    const float* __restrict__ wo,   const float* __restrict__ bo,
    const float* __restrict__ n_w1, const float* __restrict__ n_b1,
    const float* __restrict__ n_w2, const float* __restrict__ n_b2,
    const float* __restrict__ n_w3, const float* __restrict__ n_b3,
    float* __restrict__ out)
{
    extern __shared__ float sm[];
    float* sKT = sm;                // 12288  [d][192]
    float* sQT = sm + 12288;        // 8192   [d][q]    (later X0)
    float* sV  = sm + 20480;        // 12288  [192][64] (later X1)
    float* sS  = sm + 32768;        // 24576  [192][128] swz (later head weights)
    float* sBK = sm + 57344;        // 192
    float* sMK = sm + 57536;        // 192
    float* sDQ = sm + 57728;        // 128
    float* sIv = sm + 57856;        // 128    (total 57984 floats)
    __shared__ int sFl[2];

    const int tid = threadIdx.x;
    const int b   = blockIdx.x;

    if (tid == 0) { sFl[0] = 0; sFl[1] = 0; }
    __syncthreads();

    // stage K (padded), Q, V (padded)
    {
        const float4* gk = (const float4*)(g_KT + b * 11264);
        const float4* gq = (const float4*)(g_QT + b * 8192);
        const float4* gv = (const float4*)(g_V  + b * 11264);
        float4* dq = (float4*)sQT;
        for (int i = tid; i < 2816; i += 256) {          // K: 64 rows x 44 f4
            int d = i / 44, c = i - d * 44;
            *(float4*)(sKT + d * NKP + c * 4) = gk[i];
        }
        for (int i = tid; i < 2048; i += 256) dq[i] = gq[i];
        for (int i = tid; i < 2816; i += 256) {          // V: 176 rows x 16 f4
            ((float4*)sV)[ (i >> 4) * 16 + (i & 15) ] = gv[i];
        }
        // zero pads
        {
            int d = tid >> 2, c = tid & 3;               // K cols 176..191
            *(float4*)(sKT + d * NKP + 176 + c * 4) = make_float4(0.f, 0.f, 0.f, 0.f);
            int r = 176 + (tid >> 4), c2 = tid & 15;     // V rows 176..191
            *(float4*)(sV + r * 64 + c2 * 4) = make_float4(0.f, 0.f, 0.f, 0.f);
        }
    }

    // classify alive-format from first 128 words (global data, deterministic)
    if (tid < 128) {
        unsigned int v = ((const unsigned int*)alive)[tid];
        if (v == 0x3F800000u) atomicOr(&sFl[0], 1);
        else if (v > 1u)      atomicOr(&sFl[1], 1);
    }
    __syncthreads();
    const int fmt = sFl[0] ? 2 : (sFl[1] ? 0 : 1);

    if (tid < NKP) {
        int k = tid;
        float p0 = 0.f, p1 = 0.f, mk = 0.f, bkv;
        if (k < 16) {
            p0 = pred_state[(b * 16 + k) * 2];
            p1 = pred_state[(b * 16 + k) * 2 + 1];
        } else if (k < 144) {
            int j = k - 16;
            p0 = prey_state[(b * 128 + j) * 2];
            p1 = prey_state[(b * 128 + j) * 2 + 1];
            bool al;
            if (fmt == 0)      al = ((const unsigned char*)alive)[b * 128 + j] != 0;
            else if (fmt == 1) al = ((const int*)alive)[b * 128 + j] != 0;
            else               al = ((const float*)alive)[b * 128 + j] != 0.f;
            if (!al) mk = -1e9f;
        } else if (k < 176) {
            int j = k - 144;
            p0 = obst_state[(b * 32 + j) * 3];
            p1 = obst_state[(b * 32 + j) * 3 + 1];
        }
        bkv = p0 * w_pos[0] + p1 * w_pos[1];
        if (k >= 176) { bkv = 8e9f; mk = 0.f; }          // force fake keys to -1e9
        sBK[k] = bkv;
        sMK[k] = mk;
    }
    if (tid < 128) {
        int q = tid;
        bool al;
        if (fmt == 0)      al = ((const unsigned char*)alive)[b * 128 + q] != 0;
        else if (fmt == 1) al = ((const int*)alive)[b * 128 + q] != 0;
        else               al = ((const float*)alive)[b * 128 + q] != 0.f;
        sDQ[q] = al ? 0.f : 1.f;
    }
    __syncthreads();

    // GEMM1 (single pass, 12x8 tiles, 256 units):
    // S[k][q] = (K.Q - bias_k)/8 + deadq*mask_k   (bias_q cancels in softmax)
    {
        const int kg = tid >> 4, qg = tid & 15;
        float acc[12][8];
#pragma unroll
        for (int i = 0; i < 12; i++)
#pragma unroll
            for (int j = 0; j < 8; j++) acc[i][j] = 0.f;
#pragma unroll 4
        for (int d = 0; d < 64; d++) {
            float4 k0 = *(const float4*)(sKT + d * NKP + kg * 12);
            float4 k1 = *(const float4*)(sKT + d * NKP + kg * 12 + 4);
            float4 k2 = *(const float4*)(sKT + d * NKP + kg * 12 + 8);
            float4 q0 = *(const float4*)(sQT + d * 128 + qg * 8);
            float4 q1 = *(const float4*)(sQT + d * 128 + qg * 8 + 4);
            float kv[12] = {k0.x, k0.y, k0.z, k0.w, k1.x, k1.y, k1.z, k1.w, k2.x, k2.y, k2.z, k2.w};
            float qv[8]  = {q0.x, q0.y, q0.z, q0.w, q1.x, q1.y, q1.z, q1.w};
#pragma unroll
            for (int i = 0; i < 12; i++)
#pragma unroll
                for (int j = 0; j < 8; j++) acc[i][j] += kv[i] * qv[j];
        }
#pragma unroll
        for (int i = 0; i < 12; i++) {
            int r = kg * 12 + i;
            float bk = sBK[r], mk = sMK[r];
            float s[8];
#pragma unroll
            for (int j = 0; j < 8; j++)
                s[j] = (acc[i][j] - bk) * 0.125f + sDQ[qg * 8 + j] * mk;
            *(float4*)(sS + r * 128 + SWZ(qg * 2,     r) * 4) = make_float4(s[0], s[1], s[2], s[3]);
            *(float4*)(sS + r * 128 + SWZ(qg * 2 + 1, r) * 4) = make_float4(s[4], s[5], s[6], s[7]);
        }
    }
    __syncthreads();

    // softmax: 128 query-pairs, each lane of a pair owns 96 keys
    {
        int q = tid >> 1, h = tid & 1;
        int g = q >> 2, qr = q & 3;
        int k0 = h ? 96 : 0, k1 = h ? NKP : 96;
        float m = -3.4e38f;
        for (int k = k0; k < k1; k++)
            m = fmaxf(m, sS[k * 128 + SWZ(g, k) * 4 + qr]);
        m = fmaxf(m, __shfl_xor_sync(0xFFFFFFFFu, m, 1));
        float ssum = 0.f;
        for (int k = k0; k < k1; k++) {
            int idx = k * 128 + SWZ(g, k) * 4 + qr;
            float p = __expf(sS[idx] - m);
            ssum += p;
            sS[idx] = p;
        }
        ssum += __shfl_xor_sync(0xFFFFFFFFu, ssum, 1);
        if (h == 0) sIv[q] = 1.f / ssum;
    }
    __syncthreads();

    const int dg = tid & 7, tg = tid >> 3, ds = dg * 8;
    float* sX0 = sQT;
    float* sX1 = sV;
    float* sWo  = sS;            // head weights overlay sS (dead after GEMM2)
    float* sW1h = sS + 4096;
    float* sW2h = sS + 8192;
    float* sW3h = sS + 12288;

    // GEMM2: attn_out = P @ V (normalized), -> sX0 transposed swizzled
    {
        float acc[4][8];
#pragma unroll
        for (int i = 0; i < 4; i++)
#pragma unroll
            for (int j = 0; j < 8; j++) acc[i][j] = 0.f;
#pragma unroll 2
        for (int k = 0; k < NKP; k++) {
            float4 p4 = *(const float4*)(sS + k * 128 + SWZ(tg, k) * 4);
            float4 v0 = *(const float4*)(sV + k * 64 + ds);
            float4 v1 = *(const float4*)(sV + k * 64 + ds + 4);
            float pv[4] = {p4.x, p4.y, p4.z, p4.w};
            float vv[8] = {v0.x, v0.y, v0.z, v0.w, v1.x, v1.y, v1.z, v1.w};
#pragma unroll
            for (int i = 0; i < 4; i++)
#pragma unroll
                for (int j = 0; j < 8; j++) acc[i][j] += pv[i] * vv[j];
        }
        float iv[4];
#pragma unroll
        for (int i = 0; i < 4; i++) iv[i] = sIv[tg * 4 + i];
#pragma unroll
        for (int j = 0; j < 8; j++) {
            int d = ds + j;
            *(float4*)(sX0 + d * 128 + SWZ(tg, d) * 4) =
                make_float4(acc[0][j] * iv[0], acc[1][j] * iv[1],
                            acc[2][j] * iv[2], acc[3][j] * iv[3]);
        }
    }
    __syncthreads();   // sS + sV reads complete

    // stage head weights into smem (sS region)
    for (int i = tid; i < 4096; i += 256) {
        sWo[i]  = wo[i];
        sW1h[i] = n_w1[i];
        sW2h[i] = n_w2[i];
    }
    if (tid < 64) sW3h[tid] = n_w3[tid];
    __syncthreads();

    head_gemm(sX0, sWo,  bo,   sX1, tg, ds, false);
    __syncthreads();
    head_gemm(sX1, sW1h, n_b1, sX0, tg, ds, true);
    __syncthreads();
    head_gemm(sX0, sW2h, n_b2, sX1, tg, ds, true);
    __syncthreads();

    if (tid < 128) {
        int q = tid, g = q >> 2, qr = q & 3;
        float a = n_b3[0];
#pragma unroll 8
        for (int d = 0; d < 64; d++)
            a += sX1[d * 128 + SWZ(g, d) * 4 + qr] * sW3h[d];
        out[b * 128 + q] = tanhf(a);
    }
}

// ---------------------------------------------------------------------------
extern "C" void kernel_launch(void* const* d_in, const int* in_sizes, int n_in,
                              void* d_out, int out_size)
{
    const float* pred  = (const float*)d_in[0];
    const float* prey  = (const float*)d_in[1];
    const float* obst  = (const float*)d_in[2];
    const void*  alive = d_in[3];
    const float* emb   = (const float*)d_in[4];
    const float* p_w1 = (const float*)d_in[5],  *p_b1 = (const float*)d_in[6];
    const float* p_w2 = (const float*)d_in[7],  *p_b2 = (const float*)d_in[8];
    const float* y_w1 = (const float*)d_in[9],  *y_b1 = (const float*)d_in[10];
    const float* y_w2 = (const float*)d_in[11], *y_b2 = (const float*)d_in[12];
    const float* o_w1 = (const float*)d_in[13], *o_b1 = (const float*)d_in[14];
    const float* o_w2 = (const float*)d_in[15], *o_b2 = (const float*)d_in[16];
    const float* wq = (const float*)d_in[17], *bq = (const float*)d_in[18];
    const float* wk = (const float*)d_in[19], *bk = (const float*)d_in[20];
    const float* wv = (const float*)d_in[21], *bv = (const float*)d_in[22];
    const float* wo = (const float*)d_in[23], *bo = (const float*)d_in[24];
    const float* w_pos = (const float*)d_in[25];
    const float* n_w1 = (const float*)d_in[26], *n_b1 = (const float*)d_in[27];
    const float* n_w2 = (const float*)d_in[28], *n_b2 = (const float*)d_in[29];
    const float* n_w3 = (const float*)d_in[30], *n_b3 = (const float*)d_in[31];
    float* out = (float*)d_out;

    cudaFuncSetAttribute(encode_kernel, cudaFuncAttributeMaxDynamicSharedMemorySize, 25472 * 4);
    cudaFuncSetAttribute(attn_kernel,   cudaFuncAttributeMaxDynamicSharedMemorySize, 57984 * 4);

    encode_kernel<<<2816, 256, 25472 * 4>>>(pred, prey, obst, emb,
        p_w1, p_b1, p_w2, p_b2, y_w1, y_b1, y_w2, y_b2, o_w1, o_b1, o_w2, o_b2,
        wq, bq, wk, bk, wv, bv);
    attn_kernel<<<2048, 256, 57984 * 4>>>(pred, prey, obst, alive, w_pos,
        wo, bo, n_w1, n_b1, n_w2, n_b2, n_w3, n_b3, out);
}

// round 4
// speedup vs baseline: 1.4559x; 1.3368x over previous
#include <cuda_runtime.h>
#include <math.h>

#define NB   2048
#define NTOK 176
#define NQ   128

// Scratch (allocation-free rule: device globals)
__device__ float g_KT[NB * 64 * NTOK];   // [b][d][k]
__device__ float g_V [NB * NTOK * 64];   // [b][k][d]
__device__ float g_QT[NB * 64 * NQ];     // [b][d][q]

#define SWZ(g, r) ((((g) ^ (r) ^ ((r) >> 3))) & 31)

// ---------------- packed f32x2 helpers (Blackwell FFMA2) -------------------
typedef unsigned long long u64t;
__device__ __forceinline__ void fma2(u64t& acc, u64t a, u64t b) {
    asm("fma.rn.f32x2 %0, %1, %2, %0;" : "+l"(acc) : "l"(a), "l"(b));
}
__device__ __forceinline__ u64t bc2(float x) {
    u64t r; unsigned int xi = __float_as_uint(x);
    asm("mov.b64 %0, {%1, %1};" : "=l"(r) : "r"(xi));
    return r;
}
__device__ __forceinline__ float2 up2(u64t v) {
    float2 r; asm("mov.b64 {%0, %1}, %2;" : "=f"(r.x), "=f"(r.y) : "l"(v));
    return r;
}

// ---------------------------------------------------------------------------
// Kernel 1: entity FFN encoders + K/V/Q projections
// 2816 blocks x 256 threads; each block = 128 tokens of one entity type.
// ---------------------------------------------------------------------------
__global__ void __launch_bounds__(256, 2) encode_kernel(
    const float* __restrict__ pred_state, const float* __restrict__ prey_state,
    const float* __restrict__ obst_state, const float* __restrict__ emb,
    const float* __restrict__ p_w1, const float* __restrict__ p_b1,
    const float* __restrict__ p_w2, const float* __restrict__ p_b2,
    const float* __restrict__ y_w1, const float* __restrict__ y_b1,
    const float* __restrict__ y_w2, const float* __restrict__ y_b2,
    const float* __restrict__ o_w1, const float* __restrict__ o_b1,
    const float* __restrict__ o_w2, const float* __restrict__ o_b2,
    const float* __restrict__ wq, const float* __restrict__ bq,
    const float* __restrict__ wk, const float* __restrict__ bk,
    const float* __restrict__ wv, const float* __restrict__ bv)
{
    extern __shared__ float sm[];
    float* sW2 = sm;            // 4096
    float* sWK = sm + 4096;     // 4096
    float* sWV = sm + 8192;     // 4096
    float* sHQ = sm + 12288;    // 4096: H half [32][128], later WQ
    float* sX  = sm + 16384;    // [64][128] swizzled
    float* sC  = sm + 24576;    // 64
    float* sBK = sm + 24640;    // 64
    float* sBV = sm + 24704;    // 64
    float* sBQ = sm + 24768;    // 64
    float* sB1 = sm + 24832;    // 64
    float* sW1 = sm + 24896;    // 192
    float* sSt = sm + 25088;    // 384   (total 25472 floats)

    const int tid = threadIdx.x;
    const int blk = blockIdx.x;

    int type, inDim, perShift, slotBase, tok0;
    const float *state, *w1, *b1, *w2, *b2;
    if (blk < 256)       { type = 0; tok0 = blk * 128;          state = pred_state; w1 = p_w1; b1 = p_b1; w2 = p_w2; b2 = p_b2; inDim = 2; perShift = 4; slotBase = 0;   }
    else if (blk < 2304) { type = 1; tok0 = (blk - 256)  * 128; state = prey_state; w1 = y_w1; b1 = y_b1; w2 = y_w2; b2 = y_b2; inDim = 2; perShift = 7; slotBase = 16;  }
    else                 { type = 2; tok0 = (blk - 2304) * 128; state = obst_state; w1 = o_w1; b1 = o_b1; w2 = o_w2; b2 = o_b2; inDim = 3; perShift = 5; slotBase = 144; }

    for (int i = tid; i < 4096; i += 256) { sW2[i] = w2[i]; sWK[i] = wk[i]; sWV[i] = wv[i]; }
    if (tid < 64) {
        sC[tid]  = b2[tid] + emb[type * 64 + tid];
        sBK[tid] = bk[tid];
        sBV[tid] = bv[tid];
        sBQ[tid] = bq[tid];
        sB1[tid] = b1[tid];
    }
    if (tid < inDim * 64) sW1[tid] = w1[tid];
    for (int i = tid; i < 128 * inDim; i += 256) {
        int t = i / inDim, j = i - t * inDim;
        sSt[t * 3 + j] = state[(tok0 + t) * inDim + j];
    }
    __syncthreads();

    const int dg = tid & 7, tg = tid >> 3, ds = dg * 8;

    // X = H @ W2 accumulated over two 32-k halves (packed over d pairs)
    u64t accX[4][4];
#pragma unroll
    for (int i = 0; i < 4; i++)
#pragma unroll
        for (int j = 0; j < 4; j++) accX[i][j] = 0ULL;

#pragma unroll 1
    for (int h = 0; h < 2; h++) {
        for (int e = tid; e < 4096; e += 256) {
            int k = e >> 7, t = e & 127;
            int gk = h * 32 + k;
            float a = sB1[gk];
            for (int j = 0; j < inDim; j++) a += sSt[t * 3 + j] * sW1[j * 64 + gk];
            sHQ[k * 128 + t] = fmaxf(a, 0.f);
        }
        __syncthreads();
#pragma unroll 4
        for (int kk = 0; kk < 32; kk++) {
            float4 a4 = *(const float4*)(sHQ + kk * 128 + tg * 4);
            const float* wr = sW2 + (h * 32 + kk) * 64 + ds;
            ulonglong2 w01 = *(const ulonglong2*)(wr);
            ulonglong2 w23 = *(const ulonglong2*)(wr + 4);
            u64t bw[4] = {w01.x, w01.y, w23.x, w23.y};
            u64t av[4] = {bc2(a4.x), bc2(a4.y), bc2(a4.z), bc2(a4.w)};
#pragma unroll
            for (int i = 0; i < 4; i++)
#pragma unroll
                for (int j = 0; j < 4; j++) fma2(accX[i][j], av[i], bw[j]);
        }
        __syncthreads();
    }

    // write X (transposed, swizzled); prey CTAs also stream WQ into sHQ (dead)
#pragma unroll
    for (int j2 = 0; j2 < 4; j2++) {
        int d0 = ds + 2 * j2, d1 = d0 + 1;
        float c0 = sC[d0], c1 = sC[d1];
        float2 u0 = up2(accX[0][j2]), u1 = up2(accX[1][j2]);
        float2 u2 = up2(accX[2][j2]), u3 = up2(accX[3][j2]);
        *(float4*)(sX + d0 * 128 + SWZ(tg, d0) * 4) =
            make_float4(u0.x + c0, u1.x + c0, u2.x + c0, u3.x + c0);
        *(float4*)(sX + d1 * 128 + SWZ(tg, d1) * 4) =
            make_float4(u0.y + c1, u1.y + c1, u2.y + c1, u3.y + c1);
    }
    if (type == 1)
        for (int i = tid; i < 4096; i += 256) sHQ[i] = wq[i];
    __syncthreads();

    const int gT   = tok0 + tg * 4;
    const int b    = gT >> perShift;
    const int lp   = gT & ((1 << perShift) - 1);
    const int slot = slotBase + lp;

    // fused K,V projections (packed)
    {
        u64t aK[4][4], aV[4][4];
#pragma unroll
        for (int i = 0; i < 4; i++)
#pragma unroll
            for (int j = 0; j < 4; j++) { aK[i][j] = 0ULL; aV[i][j] = 0ULL; }
#pragma unroll 2
        for (int k = 0; k < 64; k++) {
            float4 a4 = *(const float4*)(sX + k * 128 + SWZ(tg, k) * 4);
            const float* kr = sWK + k * 64 + ds;
            const float* vr = sWV + k * 64 + ds;
            ulonglong2 k01 = *(const ulonglong2*)(kr);
            ulonglong2 k23 = *(const ulonglong2*)(kr + 4);
            ulonglong2 v01 = *(const ulonglong2*)(vr);
            ulonglong2 v23 = *(const ulonglong2*)(vr + 4);
            u64t kw[4] = {k01.x, k01.y, k23.x, k23.y};
            u64t vw[4] = {v01.x, v01.y, v23.x, v23.y};
            u64t av[4] = {bc2(a4.x), bc2(a4.y), bc2(a4.z), bc2(a4.w)};
#pragma unroll
            for (int i = 0; i < 4; i++)
#pragma unroll
                for (int j = 0; j < 4; j++) {
                    fma2(aK[i][j], av[i], kw[j]);
                    fma2(aV[i][j], av[i], vw[j]);
                }
        }
#pragma unroll
        for (int j2 = 0; j2 < 4; j2++) {
            int d0 = ds + 2 * j2, d1 = d0 + 1;
            float b0 = sBK[d0], b1v = sBK[d1];
            float2 u0 = up2(aK[0][j2]), u1 = up2(aK[1][j2]);
            float2 u2 = up2(aK[2][j2]), u3 = up2(aK[3][j2]);
            *(float4*)(g_KT + (b * 64 + d0) * 176 + slot) =
                make_float4(u0.x + b0, u1.x + b0, u2.x + b0, u3.x + b0);
            *(float4*)(g_KT + (b * 64 + d1) * 176 + slot) =
                make_float4(u0.y + b1v, u1.y + b1v, u2.y + b1v, u3.y + b1v);
        }
#pragma unroll
        for (int i = 0; i < 4; i++) {
            int row = (b * 176 + slot + i) * 64;
            float2 v0 = up2(aV[i][0]), v1 = up2(aV[i][1]);
            float2 v2 = up2(aV[i][2]), v3 = up2(aV[i][3]);
            *(float4*)(g_V + row + ds) =
                make_float4(v0.x + sBV[ds], v0.y + sBV[ds + 1], v1.x + sBV[ds + 2], v1.y + sBV[ds + 3]);
            *(float4*)(g_V + row + ds + 4) =
                make_float4(v2.x + sBV[ds + 4], v2.y + sBV[ds + 5], v3.x + sBV[ds + 6], v3.y + sBV[ds + 7]);
        }
    }

    if (type == 1) {
        u64t aQ[4][4];
#pragma unroll
        for (int i = 0; i < 4; i++)
#pragma unroll
            for (int j = 0; j < 4; j++) aQ[i][j] = 0ULL;
#pragma unroll 4
        for (int k = 0; k < 64; k++) {
            float4 a4 = *(const float4*)(sX + k * 128 + SWZ(tg, k) * 4);
            const float* qr = sHQ + k * 64 + ds;
            ulonglong2 q01 = *(const ulonglong2*)(qr);
            ulonglong2 q23 = *(const ulonglong2*)(qr + 4);
            u64t qw[4] = {q01.x, q01.y, q23.x, q23.y};
            u64t av[4] = {bc2(a4.x), bc2(a4.y), bc2(a4.z), bc2(a4.w)};
#pragma unroll
            for (int i = 0; i < 4; i++)
#pragma unroll
                for (int j = 0; j < 4; j++) fma2(aQ[i][j], av[i], qw[j]);
        }
#pragma unroll
        for (int j2 = 0; j2 < 4; j2++) {
            int d0 = ds + 2 * j2, d1 = d0 + 1;
            float b0 = sBQ[d0], b1v = sBQ[d1];
            float2 u0 = up2(aQ[0][j2]), u1 = up2(aQ[1][j2]);
            float2 u2 = up2(aQ[2][j2]), u3 = up2(aQ[3][j2]);
            *(float4*)(g_QT + (b * 64 + d0) * 128 + lp) =
                make_float4(u0.x + b0, u1.x + b0, u2.x + b0, u3.x + b0);
            *(float4*)(g_QT + (b * 64 + d1) * 128 + lp) =
                make_float4(u0.y + b1v, u1.y + b1v, u2.y + b1v, u3.y + b1v);
        }
    }
}

// ---------------------------------------------------------------------------
// Kernel 2: attention + head. One CTA per (batch, query-half): grid 4096.
// 64 queries per CTA; K/V time-share one buffer -> ~111KB smem -> 2 CTAs/SM.
// S layout: [176][64], float4 q-groups XOR-swizzled by row.
// ---------------------------------------------------------------------------
// head gemm: Out[d][64q] = act(A[64][64q] @ W[64][64] + bias); packed f32x2.
__device__ __forceinline__ void head_gemm64(
    const float* __restrict__ A, const float* __restrict__ W,
    const float* __restrict__ bias, float* __restrict__ Out,
    int qt, int dt, bool doRelu)
{
    u64t acc[4][2];
#pragma unroll
    for (int i = 0; i < 4; i++) { acc[i][0] = 0ULL; acc[i][1] = 0ULL; }
#pragma unroll 4
    for (int k = 0; k < 64; k++) {
        float4 a4 = *(const float4*)(A + k * 64 + ((qt ^ (k & 15)) << 2));
        ulonglong2 wv = *(const ulonglong2*)(W + k * 64 + dt * 4);
        u64t av[4] = {bc2(a4.x), bc2(a4.y), bc2(a4.z), bc2(a4.w)};
#pragma unroll
        for (int i = 0; i < 4; i++) {
            fma2(acc[i][0], av[i], wv.x);
            fma2(acc[i][1], av[i], wv.y);
        }
    }
    float2 u[4][2];
#pragma unroll
    for (int i = 0; i < 4; i++) { u[i][0] = up2(acc[i][0]); u[i][1] = up2(acc[i][1]); }
#pragma unroll
    for (int dj = 0; dj < 4; dj++) {
        int d = dt * 4 + dj;
        float bb = bias[d];
        float o0, o1, o2, o3;
        if (dj == 0)      { o0 = u[0][0].x; o1 = u[1][0].x; o2 = u[2][0].x; o3 = u[3][0].x; }
        else if (dj == 1) { o0 = u[0][0].y; o1 = u[1][0].y; o2 = u[2][0].y; o3 = u[3][0].y; }
        else if (dj == 2) { o0 = u[0][1].x; o1 = u[1][1].x; o2 = u[2][1].x; o3 = u[3][1].x; }
        else              { o0 = u[0][1].y; o1 = u[1][1].y; o2 = u[2][1].y; o3 = u[3][1].y; }
        o0 += bb; o1 += bb; o2 += bb; o3 += bb;
        if (doRelu) { o0 = fmaxf(o0, 0.f); o1 = fmaxf(o1, 0.f); o2 = fmaxf(o2, 0.f); o3 = fmaxf(o3, 0.f); }
        *(float4*)(Out + d * 64 + ((qt ^ (d & 15)) << 2)) = make_float4(o0, o1, o2, o3);
    }
}

__global__ void __launch_bounds__(256, 2) attn_kernel(
    const float* __restrict__ pred_state, const float* __restrict__ prey_state,
    const float* __restrict__ obst_state, const void* __restrict__ alive,
    const float* __restrict__ w_pos,
    const float* __restrict__ wo,   const float* __restrict__ bo,
    const float* __restrict__ n_w1, const float* __restrict__ n_b1,
    const float* __restrict__ n_w2, const float* __restrict__ n_b2,
    const float* __restrict__ n_w3, const float* __restrict__ n_b3,
    float* __restrict__ out)
{
    extern __shared__ float sm[];
    float* sKV = sm;             // 12288: K [64][192] (GEMM1), then V [176][64];
                                 //        later X1 @0, n_w2 @4096
    float* sQT = sm + 12288;     // 4096:  Q [64][64], later X0
    float* sS  = sm + 16384;     // 11264: S [176][64] swz; later wo @0, n_w1 @4096
    float* sBK = sm + 27648;     // 176
    float* sMK = sm + 27824;     // 176
    float* sDQ = sm + 28000;     // 64
    float* sIv = sm + 28064;     // 64
    float* sBo = sm + 28128;     // 64
    float* sB1h= sm + 28192;     // 64
    float* sB2h= sm + 28256;     // 64
    float* sW3h= sm + 28320;     // 64
    float* sB3 = sm + 28384;     // 1   (alloc 28416)
    __shared__ int sFl[2];

    const int tid = threadIdx.x;
    const int b   = blockIdx.x >> 1;
    const int qh  = (blockIdx.x & 1) << 6;   // query-half offset

    if (tid == 0) { sFl[0] = 0; sFl[1] = 0; }
    __syncthreads();

    // phase 1: stage K, Q, small vectors; classify alive format
    {
        const float4* gk = (const float4*)(g_KT + b * 11264);
        for (int i = tid; i < 2816; i += 256) {          // K: 64 rows x 44 f4 -> stride 192
            int d = i / 44, c = i - d * 44;
            *(float4*)(sKV + d * 192 + c * 4) = gk[i];
        }
        for (int i = tid; i < 1024; i += 256) {          // Q half: 64 rows x 16 f4
            int d = i >> 4, c = i & 15;
            *(float4*)(sQT + d * 64 + c * 4) =
                *(const float4*)(g_QT + b * 8192 + d * 128 + qh + c * 4);
        }
        if (tid < 64) {
            sBo[tid]  = bo[tid];
            sB1h[tid] = n_b1[tid];
            sB2h[tid] = n_b2[tid];
            sW3h[tid] = n_w3[tid];
        }
        if (tid == 0) sB3[0] = n_b3[0];
        if (tid < 128) {
            unsigned int v = ((const unsigned int*)alive)[tid];
            if (v == 0x3F800000u) atomicOr(&sFl[0], 1);
            else if (v > 1u)      atomicOr(&sFl[1], 1);
        }
    }
    __syncthreads();
    const int fmt = sFl[0] ? 2 : (sFl[1] ? 0 : 1);

    // phase 2: per-key bias/mask; per-(local)query dead flag
    if (tid < NTOK) {
        int k = tid;
        float p0, p1, mk = 0.f;
        if (k < 16) {
            p0 = pred_state[(b * 16 + k) * 2];
            p1 = pred_state[(b * 16 + k) * 2 + 1];
        } else if (k < 144) {
            int j = k - 16;
            p0 = prey_state[(b * 128 + j) * 2];
            p1 = prey_state[(b * 128 + j) * 2 + 1];
            bool al;
            if (fmt == 0)      al = ((const unsigned char*)alive)[b * 128 + j] != 0;
            else if (fmt == 1) al = ((const int*)alive)[b * 128 + j] != 0;
            else               al = ((const float*)alive)[b * 128 + j] != 0.f;
            if (!al) mk = -1e9f;
        } else {
            int j = k - 144;
            p0 = obst_state[(b * 32 + j) * 3];
            p1 = obst_state[(b * 32 + j) * 3 + 1];
        }
        sBK[k] = p0 * w_pos[0] + p1 * w_pos[1];
        sMK[k] = mk;
    }
    if (tid < 64) {
        int q = qh + tid;
        bool al;
        if (fmt == 0)      al = ((const unsigned char*)alive)[b * 128 + q] != 0;
        else if (fmt == 1) al = ((const int*)alive)[b * 128 + q] != 0;
        else               al = ((const float*)alive)[b * 128 + q] != 0.f;
        sDQ[tid] = al ? 0.f : 1.f;
    }
    __syncthreads();

    // GEMM1: S[k][q] = (K.Q - bias_k)/8 + deadq*mask_k (packed over key pairs)
    {
        const int kg = tid >> 4, qg = tid & 15;   // 16x12 keys, 16x4 queries
        u64t acc[6][4];
#pragma unroll
        for (int p = 0; p < 6; p++)
#pragma unroll
            for (int j = 0; j < 4; j++) acc[p][j] = 0ULL;
#pragma unroll 4
        for (int d = 0; d < 64; d++) {
            const float* kr = sKV + d * 192 + kg * 12;
            ulonglong2 kA = *(const ulonglong2*)(kr);
            ulonglong2 kB = *(const ulonglong2*)(kr + 4);
            ulonglong2 kC = *(const ulonglong2*)(kr + 8);
            float4 q4 = *(const float4*)(sQT + d * 64 + qg * 4);
            u64t kp[6] = {kA.x, kA.y, kB.x, kB.y, kC.x, kC.y};
            u64t qb[4] = {bc2(q4.x), bc2(q4.y), bc2(q4.z), bc2(q4.w)};
#pragma unroll
            for (int p = 0; p < 6; p++)
#pragma unroll
                for (int j = 0; j < 4; j++) fma2(acc[p][j], kp[p], qb[j]);
        }
        float dq[4] = {sDQ[qg * 4], sDQ[qg * 4 + 1], sDQ[qg * 4 + 2], sDQ[qg * 4 + 3]};
#pragma unroll
        for (int p = 0; p < 6; p++) {
            int r0 = kg * 12 + 2 * p, r1 = r0 + 1;
            float2 u0 = up2(acc[p][0]), u1 = up2(acc[p][1]);
            float2 u2 = up2(acc[p][2]), u3 = up2(acc[p][3]);
            if (r0 < NTOK) {
                float bk = sBK[r0], mk = sMK[r0];
                *(float4*)(sS + r0 * 64 + ((qg ^ (r0 & 15)) << 2)) =
                    make_float4((u0.x - bk) * 0.125f + dq[0] * mk,
                                (u1.x - bk) * 0.125f + dq[1] * mk,
                                (u2.x - bk) * 0.125f + dq[2] * mk,
                                (u3.x - bk) * 0.125f + dq[3] * mk);
            }
            if (r1 < NTOK) {
                float bk = sBK[r1], mk = sMK[r1];
                *(float4*)(sS + r1 * 64 + ((qg ^ (r1 & 15)) << 2)) =
                    make_float4((u0.y - bk) * 0.125f + dq[0] * mk,
                                (u1.y - bk) * 0.125f + dq[1] * mk,
                                (u2.y - bk) * 0.125f + dq[2] * mk,
                                (u3.y - bk) * 0.125f + dq[3] * mk);
            }
        }
    }
    __syncthreads();

    // phase 4: stage V into sKV (K dead) + softmax over sS
    {
        const float4* gv = (const float4*)(g_V + b * 11264);
        float4* dv = (float4*)sKV;
        for (int i = tid; i < 2816; i += 256) dv[i] = gv[i];   // V [176][64]
    }
    {
        int q = tid >> 2, sub = tid & 3;
        int g = q >> 2, qr = q & 3;
        int k0 = sub * 44, k1 = k0 + 44;
        float m = -3.4e38f;
        for (int k = k0; k < k1; k++)
            m = fmaxf(m, sS[k * 64 + ((g ^ (k & 15)) << 2) + qr]);
        m = fmaxf(m, __shfl_xor_sync(0xFFFFFFFFu, m, 1));
        m = fmaxf(m, __shfl_xor_sync(0xFFFFFFFFu, m, 2));
        float ssum = 0.f;
        for (int k = k0; k < k1; k++) {
            int idx = k * 64 + ((g ^ (k & 15)) << 2) + qr;
            float p = __expf(sS[idx] - m);
            ssum += p;
            sS[idx] = p;
        }
        ssum += __shfl_xor_sync(0xFFFFFFFFu, ssum, 1);
        ssum += __shfl_xor_sync(0xFFFFFFFFu, ssum, 2);
        if (sub == 0) sIv[q] = 1.f / ssum;
    }
    __syncthreads();

    const int qt = tid & 15, dt = tid >> 4;
    float* sX0 = sQT;
    float* sX1 = sKV;            // after GEMM2, V dead
    float* sWo  = sS;
    float* sW1h = sS + 4096;
    float* sW2h = sKV + 4096;

    // GEMM2: X0[d][q] = (P @ V)[q][d] * iv[q]  (packed over d pairs)
    {
        u64t acc[4][2];
#pragma unroll
        for (int i = 0; i < 4; i++) { acc[i][0] = 0ULL; acc[i][1] = 0ULL; }
#pragma unroll 4
        for (int k = 0; k < NTOK; k++) {
            float4 p4 = *(const float4*)(sS + k * 64 + ((qt ^ (k & 15)) << 2));
            ulonglong2 vv = *(const ulonglong2*)(sKV + k * 64 + dt * 4);
            u64t pv[4] = {bc2(p4.x), bc2(p4.y), bc2(p4.z), bc2(p4.w)};
#pragma unroll
            for (int i = 0; i < 4; i++) {
                fma2(acc[i][0], pv[i], vv.x);
                fma2(acc[i][1], pv[i], vv.y);
            }
        }
        float iv[4] = {sIv[qt * 4], sIv[qt * 4 + 1], sIv[qt * 4 + 2], sIv[qt * 4 + 3]};
        float2 u[4][2];
#pragma unroll
        for (int i = 0; i < 4; i++) {
            u[i][0] = up2(acc[i][0]); u[i][1] = up2(acc[i][1]);
        }
        __syncthreads();   // all P/V reads done before X0 overwrites sQT? X0 IS sQT (Q dead) — and sS/sKV still intact; sync orders nothing harmful
#pragma unroll
        for (int dj = 0; dj < 4; dj++) {
            int d = dt * 4 + dj;
            float o0, o1, o2, o3;
            if (dj == 0)      { o0 = u[0][0].x; o1 = u[1][0].x; o2 = u[2][0].x; o3 = u[3][0].x; }
            else if (dj == 1) { o0 = u[0][0].y; o1 = u[1][0].y; o2 = u[2][0].y; o3 = u[3][0].y; }
            else if (dj == 2) { o0 = u[0][1].x; o1 = u[1][1].x; o2 = u[2][1].x; o3 = u[3][1].x; }
            else              { o0 = u[0][1].y; o1 = u[1][1].y; o2 = u[2][1].y; o3 = u[3][1].y; }
            *(float4*)(sX0 + d * 64 + ((qt ^ (d & 15)) << 2)) =
                make_float4(o0 * iv[0], o1 * iv[1], o2 * iv[2], o3 * iv[3]);
        }
    }
    __syncthreads();

    // stage head weights (sS and upper sKV are dead now)
    for (int i = tid; i < 4096; i += 256) {
        sWo[i]  = wo[i];
        sW1h[i] = n_w1[i];
        sW2h[i] = n_w2[i];
    }
    __syncthreads();

    head_gemm64(sX0, sWo,  sBo,  sX1, qt, dt, false);
    __syncthreads();
    head_gemm64(sX1, sW1h, sB1h, sX0, qt, dt, true);
    __syncthreads();
    head_gemm64(sX0, sW2h, sB2h, sX1, qt, dt, true);
    __syncthreads();

    // final: out[q] = tanh(X1[:,q] . n_w3 + b3); 4 threads per query
    {
        int q = tid >> 2, sub = tid & 3;
        int g = q >> 2, qr = q & 3;
        float a = 0.f;
#pragma unroll 4
        for (int dd = 0; dd < 16; dd++) {
            int d = sub * 16 + dd;
            a += sX1[d * 64 + ((g ^ (d & 15)) << 2) + qr] * sW3h[d];
        }
        a += __shfl_xor_sync(0xFFFFFFFFu, a, 1);
        a += __shfl_xor_sync(0xFFFFFFFFu, a, 2);
        if (sub == 0) out[b * 128 + qh + q] = tanhf(a + sB3[0]);
    }
}

// ---------------------------------------------------------------------------
extern "C" void kernel_launch(void* const* d_in, const int* in_sizes, int n_in,
                              void* d_out, int out_size)
{
    const float* pred  = (const float*)d_in[0];
    const float* prey  = (const float*)d_in[1];
    const float* obst  = (const float*)d_in[2];
    const void*  alive = d_in[3];
    const float* emb   = (const float*)d_in[4];
    const float* p_w1 = (const float*)d_in[5],  *p_b1 = (const float*)d_in[6];
    const float* p_w2 = (const float*)d_in[7],  *p_b2 = (const float*)d_in[8];
    const float* y_w1 = (const float*)d_in[9],  *y_b1 = (const float*)d_in[10];
    const float* y_w2 = (const float*)d_in[11], *y_b2 = (const float*)d_in[12];
    const float* o_w1 = (const float*)d_in[13], *o_b1 = (const float*)d_in[14];
    const float* o_w2 = (const float*)d_in[15], *o_b2 = (const float*)d_in[16];
    const float* wq = (const float*)d_in[17], *bq = (const float*)d_in[18];
    const float* wk = (const float*)d_in[19], *bk = (const float*)d_in[20];
    const float* wv = (const float*)d_in[21], *bv = (const float*)d_in[22];
    const float* wo = (const float*)d_in[23], *bo = (const float*)d_in[24];
    const float* w_pos = (const float*)d_in[25];
    const float* n_w1 = (const float*)d_in[26], *n_b1 = (const float*)d_in[27];
    const float* n_w2 = (const float*)d_in[28], *n_b2 = (const float*)d_in[29];
    const float* n_w3 = (const float*)d_in[30], *n_b3 = (const float*)d_in[31];
    float* out = (float*)d_out;

    cudaFuncSetAttribute(encode_kernel, cudaFuncAttributeMaxDynamicSharedMemorySize, 25472 * 4);
    cudaFuncSetAttribute(attn_kernel,   cudaFuncAttributeMaxDynamicSharedMemorySize, 28416 * 4);

    encode_kernel<<<2816, 256, 25472 * 4>>>(pred, prey, obst, emb,
        p_w1, p_b1, p_w2, p_b2, y_w1, y_b1, y_w2, y_b2, o_w1, o_b1, o_w2, o_b2,
        wq, bq, wk, bk, wv, bv);
    attn_kernel<<<4096, 256, 28416 * 4>>>(pred, prey, obst, alive, w_pos,
        wo, bo, n_w1, n_b1, n_w2, n_b2, n_w3, n_b3, out);
}